// round 1
// baseline (speedup 1.0000x reference)
#include <cuda_runtime.h>
#include <math.h>

#define N_NODES 100000
#define N_EDGES 1600000
#define HID 128
#define OUTD 4
#define N_EXP 4
#define NUM_GRAPHS 64
#define PRIOR_W 0.35f

// ---------------- scratch layout (floats) ----------------
#define OFF_H      0ull
#define OFF_AGGH   (OFF_H    + (unsigned long long)N_NODES*HID)
#define OFF_Z1     (OFF_AGGH + (unsigned long long)N_NODES*HID)
#define OFF_AGGZ   (OFF_Z1   + (unsigned long long)N_NODES*HID)
#define OFF_Z2     (OFF_AGGZ + (unsigned long long)N_NODES*HID)
#define OFF_U      (OFF_Z2   + (unsigned long long)N_NODES*HID)
#define OFF_R      (OFF_U    + (unsigned long long)N_NODES*OUTD)
#define OFF_AGG4   (OFF_R    + (unsigned long long)N_NODES*OUTD)
#define OFF_GW     (OFF_AGG4 + (unsigned long long)N_NODES*OUTD)
#define OFF_NCNT   (OFF_GW   + (unsigned long long)N_NODES*N_EXP)
#define OFF_ECNT   (OFF_NCNT + NUM_GRAPHS)
#define OFF_SF     (OFF_ECNT + NUM_GRAPHS)
#define OFF_LNN    (OFF_SF   + NUM_GRAPHS*3)
#define TOTAL_F    (OFF_LNN  + NUM_GRAPHS)

__device__ __align__(16) float g_buf[TOTAL_F];

// ---------------- encoder: h = relu(x[:,4:10]@W1+b1)@W2+b2 ----------------
__global__ void k_encoder(const float* __restrict__ x,
                          const float* __restrict__ W1, const float* __restrict__ b1,
                          const float* __restrict__ W2, const float* __restrict__ b2,
                          float* __restrict__ h) {
    __shared__ float xs[8][8];
    __shared__ float h1[8][HID];
    int n0 = blockIdx.x * 8;
    int t = threadIdx.x;
    if (t < 48) {
        int j = t / 6, f = t % 6;
        int node = n0 + j;
        xs[j][f] = (node < N_NODES) ? x[(size_t)node * 16 + 4 + f] : 0.f;
    }
    __syncthreads();
    float bb1 = b1[t];
    #pragma unroll
    for (int j = 0; j < 8; ++j) {
        float acc = bb1;
        #pragma unroll
        for (int f = 0; f < 6; ++f) acc += xs[j][f] * __ldg(&W1[f * HID + t]);
        h1[j][t] = fmaxf(acc, 0.f);
    }
    __syncthreads();
    float bb2 = b2[t];
    for (int j = 0; j < 8; ++j) {
        int node = n0 + j;
        if (node >= N_NODES) break;
        float acc = bb2;
        #pragma unroll 8
        for (int k = 0; k < HID; ++k) acc += h1[j][k] * __ldg(&W2[k * HID + t]);
        h[(size_t)node * HID + t] = acc;
    }
}

// ---------------- node counts: batch is sorted -> binary search ----------------
__global__ void k_node_count(const int* __restrict__ batch, float* __restrict__ ncnt) {
    int g = threadIdx.x;
    if (g >= NUM_GRAPHS) return;
    int lo = 0, hi = N_NODES;
    while (lo < hi) { int m = (lo + hi) >> 1; if (batch[m] < g) lo = m + 1; else hi = m; }
    int a = lo;
    lo = 0; hi = N_NODES;
    while (lo < hi) { int m = (lo + hi) >> 1; if (batch[m] < g + 1) lo = m + 1; else hi = m; }
    ncnt[g] = (float)(lo - a);
}

// ---------------- edge counts over batch[src] ----------------
__global__ void k_edge_count(const int* __restrict__ src, const int* __restrict__ batch,
                             float* __restrict__ ecnt) {
    __shared__ float sc[NUM_GRAPHS];
    int t = threadIdx.x;
    if (t < NUM_GRAPHS) sc[t] = 0.f;
    __syncthreads();
    for (int e = blockIdx.x * blockDim.x + t; e < N_EDGES; e += gridDim.x * blockDim.x)
        atomicAdd(&sc[batch[src[e]]], 1.f);
    __syncthreads();
    if (t < NUM_GRAPHS) atomicAdd(&ecnt[t], sc[t]);
}

// ---------------- per-graph stats (single block, 64 threads) ----------------
__global__ void k_stats(const float* __restrict__ ncnt, const float* __restrict__ ecnt,
                        float* __restrict__ sf, float* __restrict__ lnn) {
    __shared__ float nn[64], ee[64], dd[64], ll[64];
    __shared__ float mean[3], istd[3], lmin, lrange;
    int g = threadIdx.x;
    float n = fmaxf(ncnt[g], 1.f);
    float e = ecnt[g];
    float d = e / fmaxf(n * (n - 1.f), 1.f);
    float lg = logf(n);
    nn[g] = n; ee[g] = e; dd[g] = d; ll[g] = lg;
    __syncthreads();
    if (g == 0) {
        double s0 = 0, s1 = 0, s2 = 0;
        float mn = ll[0], mx = ll[0];
        for (int i = 0; i < 64; ++i) {
            s0 += nn[i]; s1 += ee[i]; s2 += dd[i];
            mn = fminf(mn, ll[i]); mx = fmaxf(mx, ll[i]);
        }
        double m0 = s0 / 64, m1 = s1 / 64, m2 = s2 / 64;
        double v0 = 0, v1 = 0, v2 = 0;
        for (int i = 0; i < 64; ++i) {
            double a = nn[i] - m0, b = ee[i] - m1, c = dd[i] - m2;
            v0 += a * a; v1 += b * b; v2 += c * c;
        }
        mean[0] = (float)m0; mean[1] = (float)m1; mean[2] = (float)m2;
        istd[0] = 1.f / ((float)sqrt(v0 / 64) + 1e-6f);
        istd[1] = 1.f / ((float)sqrt(v1 / 64) + 1e-6f);
        istd[2] = 1.f / ((float)sqrt(v2 / 64) + 1e-6f);
        lmin = mn; lrange = mx - mn + 1e-6f;
    }
    __syncthreads();
    sf[g * 3 + 0] = (nn[g] - mean[0]) * istd[0];
    sf[g * 3 + 1] = (ee[g] - mean[1]) * istd[1];
    sf[g * 3 + 2] = (dd[g] - mean[2]) * istd[2];
    lnn[g] = (ll[g] - lmin) / lrange;
}

// ---------------- router + gating weights ----------------
#define RNB 4
__global__ void k_router(const float* __restrict__ h, const int* __restrict__ batch,
                         const float* __restrict__ sf, const float* __restrict__ lnn,
                         const float* __restrict__ W1, const float* __restrict__ b1,
                         const float* __restrict__ W2, const float* __restrict__ b2,
                         const float* __restrict__ centers, float* __restrict__ w) {
    __shared__ float hs[RNB][132];
    __shared__ float hid[RNB][HID];
    __shared__ float lgts[RNB][4];
    __shared__ float lnode[RNB];
    int n0 = blockIdx.x * RNB;
    int t = threadIdx.x;
    for (int j = 0; j < RNB; ++j) {
        int node = n0 + j;
        hs[j][t] = (node < N_NODES) ? h[(size_t)node * HID + t] : 0.f;
    }
    if (t < RNB) {
        int node = n0 + t;
        int b = (node < N_NODES) ? batch[node] : 0;
        hs[t][128] = sf[b * 3 + 0];
        hs[t][129] = sf[b * 3 + 1];
        hs[t][130] = sf[b * 3 + 2];
        lnode[t] = lnn[b];
    }
    __syncthreads();
    float bb = b1[t];
    for (int j = 0; j < RNB; ++j) {
        float acc = bb;
        #pragma unroll 8
        for (int k = 0; k < 131; ++k) acc += hs[j][k] * __ldg(&W1[k * HID + t]);
        hid[j][t] = fmaxf(acc, 0.f);
    }
    __syncthreads();
    int e = t >> 5, lane = t & 31;
    for (int j = 0; j < RNB; ++j) {
        float p = 0.f;
        for (int k = lane; k < HID; k += 32) p += hid[j][k] * __ldg(&W2[k * 4 + e]);
        #pragma unroll
        for (int o = 16; o; o >>= 1) p += __shfl_down_sync(0xffffffffu, p, o);
        if (lane == 0) lgts[j][e] = p + b2[e];
    }
    __syncthreads();
    if (t < RNB) {
        int node = n0 + t;
        if (node < N_NODES) {
            float l[4];
            float ln = lnode[t];
            #pragma unroll
            for (int i = 0; i < 4; ++i) {
                float pr = ln - centers[i];
                l[i] = (1.f - PRIOR_W) * lgts[t][i] - PRIOR_W * pr * pr;
            }
            float m = fmaxf(fmaxf(l[0], l[1]), fmaxf(l[2], l[3]));
            float p[4], s = 0.f;
            #pragma unroll
            for (int i = 0; i < 4; ++i) { p[i] = expf(l[i] - m); s += p[i]; }
            #pragma unroll
            for (int i = 0; i < 4; ++i) p[i] /= s;
            int i1 = 0;
            for (int i = 1; i < 4; ++i) if (p[i] > p[i1]) i1 = i;
            int i2 = -1;
            for (int i = 0; i < 4; ++i) { if (i == i1) continue; if (i2 < 0 || p[i] > p[i2]) i2 = i; }
            float inv = 1.f / (p[i1] + p[i2] + 1e-8f);
            float ww[4] = {0.f, 0.f, 0.f, 0.f};
            ww[i1] = p[i1] * inv; ww[i2] = p[i2] * inv;
            #pragma unroll
            for (int i = 0; i < 4; ++i) w[(size_t)node * 4 + i] = ww[i];
        }
    }
}

// ---------------- fused dual GEMM: out = act(A@Wa + B@Wb + bias) ----------------
// A,B: [N,128]; Wa,Wb: [128,128] (k-major); tile 64 rows x 128 cols, K=256.
__global__ __launch_bounds__(256) void k_linear_dual(
    const float* __restrict__ A, const float* __restrict__ B,
    const float* __restrict__ Wa, const float* __restrict__ Wb,
    const float* __restrict__ bias, float* __restrict__ out, int do_relu) {
    __shared__ float Xs[64][32];
    __shared__ float Ws[32][128];
    int tid = threadIdx.x;
    int tx = tid & 31, ty = tid >> 5;
    int row0 = blockIdx.x * 64;
    float acc[8][4];
    #pragma unroll
    for (int j = 0; j < 8; ++j)
        #pragma unroll
        for (int c = 0; c < 4; ++c) acc[j][c] = 0.f;

    int lnode = tid >> 2;            // 0..63
    int lkc = (tid & 3) * 8;         // 0,8,16,24

    for (int kt = 0; kt < 8; ++kt) {
        int k0 = kt * 32;
        const float* Wsrc = (k0 < 128) ? (Wa + (size_t)k0 * HID) : (Wb + (size_t)(k0 - 128) * HID);
        const float4* ws4 = (const float4*)Wsrc;
        float4* wd4 = (float4*)&Ws[0][0];
        #pragma unroll
        for (int i = tid; i < 32 * 128 / 4; i += 256) wd4[i] = ws4[i];

        const float* Xsrc = (k0 < 128) ? A : B;
        int kk0 = k0 & 127;
        int gr = row0 + lnode;
        float4 v0 = make_float4(0.f, 0.f, 0.f, 0.f), v1 = v0;
        if (gr < N_NODES) {
            const float* p = Xsrc + (size_t)gr * HID + kk0 + lkc;
            v0 = *(const float4*)p;
            v1 = *(const float4*)(p + 4);
        }
        *(float4*)&Xs[lnode][lkc] = v0;
        *(float4*)&Xs[lnode][lkc + 4] = v1;
        __syncthreads();

        #pragma unroll
        for (int k = 0; k < 32; ++k) {
            float4 wv = *(const float4*)&Ws[k][tx * 4];
            #pragma unroll
            for (int j = 0; j < 8; ++j) {
                float a = Xs[ty * 8 + j][k];
                acc[j][0] += a * wv.x;
                acc[j][1] += a * wv.y;
                acc[j][2] += a * wv.z;
                acc[j][3] += a * wv.w;
            }
        }
        __syncthreads();
    }
    float4 bb = *(const float4*)&bias[tx * 4];
    #pragma unroll
    for (int j = 0; j < 8; ++j) {
        int gr = row0 + ty * 8 + j;
        if (gr < N_NODES) {
            float4 o;
            o.x = acc[j][0] + bb.x; o.y = acc[j][1] + bb.y;
            o.z = acc[j][2] + bb.z; o.w = acc[j][3] + bb.w;
            if (do_relu) {
                o.x = fmaxf(o.x, 0.f); o.y = fmaxf(o.y, 0.f);
                o.z = fmaxf(o.z, 0.f); o.w = fmaxf(o.w, 0.f);
            }
            *(float4*)&out[(size_t)gr * HID + tx * 4] = o;
        }
    }
}

// ---------------- 128-wide scatter-add: agg[dst] += z[src] (warp per edge) ----------------
__global__ void k_scatter128(const float* __restrict__ z, const int* __restrict__ src,
                             const int* __restrict__ dst, float* __restrict__ agg) {
    int idx = blockIdx.x * blockDim.x + threadIdx.x;
    int e = idx >> 5;
    if (e >= N_EDGES) return;
    int lane = idx & 31;
    int s = __ldg(&src[e]);
    int d = __ldg(&dst[e]);
    float4 v = *(const float4*)&z[(size_t)s * HID + lane * 4];
    float* p = &agg[(size_t)d * HID + lane * 4];
    asm volatile("red.global.add.v4.f32 [%0], {%1,%2,%3,%4};"
                 :: "l"(p), "f"(v.x), "f"(v.y), "f"(v.z), "f"(v.w) : "memory");
}

// ---------------- 4-wide scatter-add (thread per edge) ----------------
__global__ void k_scatter4(const float* __restrict__ u, const int* __restrict__ src,
                           const int* __restrict__ dst, float* __restrict__ agg) {
    int e = blockIdx.x * blockDim.x + threadIdx.x;
    if (e >= N_EDGES) return;
    int s = __ldg(&src[e]);
    int d = __ldg(&dst[e]);
    float4 v = *(const float4*)&u[(size_t)s * 4];
    float* p = &agg[(size_t)d * 4];
    asm volatile("red.global.add.v4.f32 [%0], {%1,%2,%3,%4};"
                 :: "l"(p), "f"(v.x), "f"(v.y), "f"(v.z), "f"(v.w) : "memory");
}

// ---------------- end layer: u = z2@eW [N,4], r = z2@erW [N,4] (warp per node) ---------
__global__ void k_end(const float* __restrict__ z2, const float* __restrict__ eW,
                      const float* __restrict__ erW, float* __restrict__ u,
                      float* __restrict__ r) {
    int node = (blockIdx.x * blockDim.x + threadIdx.x) >> 5;
    int lane = threadIdx.x & 31;
    if (node >= N_NODES) return;
    float au[4] = {0.f, 0.f, 0.f, 0.f}, ar[4] = {0.f, 0.f, 0.f, 0.f};
    const float* zr = z2 + (size_t)node * HID;
    for (int k = lane; k < HID; k += 32) {
        float zv = zr[k];
        float4 wa = *(const float4*)&eW[k * 4];
        float4 wb = *(const float4*)&erW[k * 4];
        au[0] += zv * wa.x; au[1] += zv * wa.y; au[2] += zv * wa.z; au[3] += zv * wa.w;
        ar[0] += zv * wb.x; ar[1] += zv * wb.y; ar[2] += zv * wb.z; ar[3] += zv * wb.w;
    }
    #pragma unroll
    for (int i = 0; i < 4; ++i) {
        #pragma unroll
        for (int o = 16; o; o >>= 1) {
            au[i] += __shfl_down_sync(0xffffffffu, au[i], o);
            ar[i] += __shfl_down_sync(0xffffffffu, ar[i], o);
        }
    }
    if (lane == 0) {
        *(float4*)&u[(size_t)node * 4] = make_float4(au[0], au[1], au[2], au[3]);
        *(float4*)&r[(size_t)node * 4] = make_float4(ar[0], ar[1], ar[2], ar[3]);
    }
}

// ---------------- final: out += (agg4 + eb + r) * w[:,e] ----------------
__global__ void k_final(const float* __restrict__ agg4, const float* __restrict__ r,
                        const float* __restrict__ eb, const float* __restrict__ w,
                        int e, int accum, float* __restrict__ out) {
    int i = blockIdx.x * blockDim.x + threadIdx.x;
    if (i >= N_NODES) return;
    float we = w[(size_t)i * 4 + e];
    float4 a = *(const float4*)&agg4[(size_t)i * 4];
    float4 rr = *(const float4*)&r[(size_t)i * 4];
    float b0 = eb[0], b1 = eb[1], b2 = eb[2], b3 = eb[3];
    float4 o;
    o.x = (a.x + b0 + rr.x) * we;
    o.y = (a.y + b1 + rr.y) * we;
    o.z = (a.z + b2 + rr.z) * we;
    o.w = (a.w + b3 + rr.w) * we;
    if (accum) {
        float4 prev = *(const float4*)&out[(size_t)i * 4];
        o.x += prev.x; o.y += prev.y; o.z += prev.z; o.w += prev.w;
    }
    *(float4*)&out[(size_t)i * 4] = o;
}

// ---------------- host ----------------
extern "C" void kernel_launch(void* const* d_in, const int* in_sizes, int n_in,
                              void* d_out, int out_size) {
    const float* x       = (const float*)d_in[0];
    const int*   ei      = (const int*)d_in[1];
    const int*   src     = ei;
    const int*   dst     = ei + N_EDGES;
    const int*   batch   = (const int*)d_in[2];
    const float* encW1   = (const float*)d_in[3];
    const float* encb1   = (const float*)d_in[4];
    const float* encW2   = (const float*)d_in[5];
    const float* encb2   = (const float*)d_in[6];
    const float* rtW1    = (const float*)d_in[7];
    const float* rtb1    = (const float*)d_in[8];
    const float* rtW2    = (const float*)d_in[9];
    const float* rtb2    = (const float*)d_in[10];
    const float* centers = (const float*)d_in[11];
    const float* sRelW   = (const float*)d_in[12];
    const float* sRelB   = (const float*)d_in[13];
    const float* sRootW  = (const float*)d_in[14];
    const float* mRelW   = (const float*)d_in[15];
    const float* mRelB   = (const float*)d_in[16];
    const float* mRootW  = (const float*)d_in[17];
    const float* eRelW   = (const float*)d_in[18];
    const float* eRelB   = (const float*)d_in[19];
    const float* eRootW  = (const float*)d_in[20];
    float* out = (float*)d_out;

    float* buf = nullptr;
    cudaGetSymbolAddress((void**)&buf, g_buf);
    float* H    = buf + OFF_H;
    float* AGGH = buf + OFF_AGGH;
    float* Z1   = buf + OFF_Z1;
    float* AGGZ = buf + OFF_AGGZ;
    float* Z2   = buf + OFF_Z2;
    float* U    = buf + OFF_U;
    float* R    = buf + OFF_R;
    float* AGG4 = buf + OFF_AGG4;
    float* GW   = buf + OFF_GW;
    float* NCNT = buf + OFF_NCNT;
    float* ECNT = buf + OFF_ECNT;
    float* SF   = buf + OFF_SF;
    float* LNN  = buf + OFF_LNN;

    // encoder
    k_encoder<<<(N_NODES + 7) / 8, 128>>>(x, encW1, encb1, encW2, encb2, H);

    // graph stats
    k_node_count<<<1, 64>>>(batch, NCNT);
    cudaMemsetAsync(ECNT, 0, NUM_GRAPHS * sizeof(float));
    k_edge_count<<<1024, 256>>>(src, batch, ECNT);
    k_stats<<<1, 64>>>(NCNT, ECNT, SF, LNN);

    // router
    k_router<<<(N_NODES + RNB - 1) / RNB, 128>>>(H, batch, SF, LNN,
                                                 rtW1, rtb1, rtW2, rtb2, centers, GW);

    // shared start-layer aggregation (expert-independent!)
    cudaMemsetAsync(AGGH, 0, (size_t)N_NODES * HID * sizeof(float));
    k_scatter128<<<N_EDGES / 8, 256>>>(H, src, dst, AGGH);

    int gemm_blocks = (N_NODES + 63) / 64;
    for (int e = 0; e < N_EXP; ++e) {
        // start: z1 = relu(aggh@sW + sb + h@srW)
        k_linear_dual<<<gemm_blocks, 256>>>(AGGH, H,
            sRelW + (size_t)e * HID * HID, sRootW + (size_t)e * HID * HID,
            sRelB + (size_t)e * HID, Z1, 1);
        // mid agg + linear
        cudaMemsetAsync(AGGZ, 0, (size_t)N_NODES * HID * sizeof(float));
        k_scatter128<<<N_EDGES / 8, 256>>>(Z1, src, dst, AGGZ);
        k_linear_dual<<<gemm_blocks, 256>>>(AGGZ, Z1,
            mRelW + (size_t)e * HID * HID, mRootW + (size_t)e * HID * HID,
            mRelB + (size_t)e * HID, Z2, 1);
        // end: project first (agg is linear), aggregate 4-wide
        k_end<<<(N_NODES + 7) / 8, 256>>>(Z2, eRelW + (size_t)e * HID * OUTD,
                                          eRootW + (size_t)e * HID * OUTD, U, R);
        cudaMemsetAsync(AGG4, 0, (size_t)N_NODES * OUTD * sizeof(float));
        k_scatter4<<<(N_EDGES + 255) / 256, 256>>>(U, src, dst, AGG4);
        k_final<<<(N_NODES + 255) / 256, 256>>>(AGG4, R, eRelB + (size_t)e * OUTD,
                                                GW, e, e > 0, out);
    }
}